// round 1
// baseline (speedup 1.0000x reference)
#include <cuda_runtime.h>
#include <math.h>

#define NN 50000
#define NE 600000
#define IN_DIM 512
#define HIDDEN 128
#define OUT_DIM 64
#define N_LAYERS 3
#define EPS 0.1f

// ---------------- scratch (static device globals; no allocation) ----------------
__device__ float g_deg[NN];                 // degree, then reused as dinv
__device__ float g_norm[NE];
__device__ float g_coef[NE];
__device__ float g_al[NN];
__device__ float g_ar[NN];
__device__ float g_raw[(size_t)NN * HIDDEN];
__device__ float g_hA[(size_t)NN * HIDDEN];
__device__ float g_hB[(size_t)NN * HIDDEN];

// ---------------- degree / norm ----------------
__global__ void k_zero_deg() {
    int i = blockIdx.x * blockDim.x + threadIdx.x;
    if (i < NN) g_deg[i] = 0.f;
}

__global__ void k_deg(const int* __restrict__ dst, int E) {
    int e = blockIdx.x * blockDim.x + threadIdx.x;
    if (e < E) atomicAdd(&g_deg[dst[e]], 1.0f);
}

__global__ void k_dinv() {
    int i = blockIdx.x * blockDim.x + threadIdx.x;
    if (i < NN) {
        float d = g_deg[i];
        g_deg[i] = (d > 0.f) ? (1.0f / sqrtf(d)) : 0.f;
    }
}

__global__ void k_norm(const int* __restrict__ src, const int* __restrict__ dst, int E) {
    int e = blockIdx.x * blockDim.x + threadIdx.x;
    if (e < E) g_norm[e] = g_deg[src[e]] * g_deg[dst[e]];
}

// ---------------- GEMM1: h = relu(x @ t1_w^T + b)  [M,512]x[128,512]^T -> [M,128] ----------------
__global__ __launch_bounds__(256, 2) void k_gemm1(const float* __restrict__ X,
                                                  const float* __restrict__ W,
                                                  const float* __restrict__ B,
                                                  float* __restrict__ O, int M) {
    __shared__ float As[8][128];
    __shared__ float Bs[8][128];
    const int tid = threadIdx.x;
    const int m0 = blockIdx.x * 128;
    const int lr = tid >> 1;          // 0..127
    const int lk = (tid & 1) * 4;     // 0 or 4
    const int tm = (tid >> 4) * 8;    // 0..120
    const int tn = (tid & 15) * 8;    // 0..120

    int gm = m0 + lr;
    if (gm >= M) gm = M - 1;
    const float* xp = X + (size_t)gm * IN_DIM + lk;
    const float* wp = W + (size_t)lr * IN_DIM + lk;

    float acc[8][8];
#pragma unroll
    for (int i = 0; i < 8; i++)
#pragma unroll
        for (int j = 0; j < 8; j++) acc[i][j] = 0.f;

    for (int k0 = 0; k0 < IN_DIM; k0 += 8) {
        float4 xa = *(const float4*)(xp + k0);
        float4 wa = *(const float4*)(wp + k0);
        As[lk + 0][lr] = xa.x; As[lk + 1][lr] = xa.y;
        As[lk + 2][lr] = xa.z; As[lk + 3][lr] = xa.w;
        Bs[lk + 0][lr] = wa.x; Bs[lk + 1][lr] = wa.y;
        Bs[lk + 2][lr] = wa.z; Bs[lk + 3][lr] = wa.w;
        __syncthreads();
#pragma unroll
        for (int kk = 0; kk < 8; kk++) {
            float4 a0 = *(const float4*)&As[kk][tm];
            float4 a1 = *(const float4*)&As[kk][tm + 4];
            float4 b0 = *(const float4*)&Bs[kk][tn];
            float4 b1 = *(const float4*)&Bs[kk][tn + 4];
            float a[8] = {a0.x, a0.y, a0.z, a0.w, a1.x, a1.y, a1.z, a1.w};
            float b[8] = {b0.x, b0.y, b0.z, b0.w, b1.x, b1.y, b1.z, b1.w};
#pragma unroll
            for (int i = 0; i < 8; i++)
#pragma unroll
                for (int j = 0; j < 8; j++) acc[i][j] = fmaf(a[i], b[j], acc[i][j]);
        }
        __syncthreads();
    }

    float bias[8];
#pragma unroll
    for (int j = 0; j < 8; j++) bias[j] = B[tn + j];
#pragma unroll
    for (int i = 0; i < 8; i++) {
        int m = m0 + tm + i;
        if (m < M) {
            float4 v0, v1;
            v0.x = fmaxf(acc[i][0] + bias[0], 0.f);
            v0.y = fmaxf(acc[i][1] + bias[1], 0.f);
            v0.z = fmaxf(acc[i][2] + bias[2], 0.f);
            v0.w = fmaxf(acc[i][3] + bias[3], 0.f);
            v1.x = fmaxf(acc[i][4] + bias[4], 0.f);
            v1.y = fmaxf(acc[i][5] + bias[5], 0.f);
            v1.z = fmaxf(acc[i][6] + bias[6], 0.f);
            v1.w = fmaxf(acc[i][7] + bias[7], 0.f);
            *(float4*)(O + (size_t)m * HIDDEN + tn) = v0;
            *(float4*)(O + (size_t)m * HIDDEN + tn + 4) = v1;
        }
    }
}

// ---------------- per-node attention dots: al = h.att_l, ar = h.att_r ----------------
__global__ __launch_bounds__(256) void k_att(const float4* __restrict__ h4,
                                             const float4* __restrict__ attl4,
                                             const float4* __restrict__ attr4, int M) {
    int w = (blockIdx.x * blockDim.x + threadIdx.x) >> 5;
    int lane = threadIdx.x & 31;
    if (w >= M) return;
    float4 hv = h4[(size_t)w * 32 + lane];
    float4 wl = attl4[lane];
    float4 wr = attr4[lane];
    float a = hv.x * wl.x + hv.y * wl.y + hv.z * wl.z + hv.w * wl.w;
    float b = hv.x * wr.x + hv.y * wr.y + hv.z * wr.z + hv.w * wr.w;
#pragma unroll
    for (int off = 16; off > 0; off >>= 1) {
        a += __shfl_xor_sync(0xffffffffu, a, off);
        b += __shfl_xor_sync(0xffffffffu, b, off);
    }
    if (lane == 0) { g_al[w] = a; g_ar[w] = b; }
}

// ---------------- per-edge coefficient: tanh(al[src]+ar[dst]) * norm ----------------
__global__ void k_coef(const int* __restrict__ src, const int* __restrict__ dst, int E) {
    int e = blockIdx.x * blockDim.x + threadIdx.x;
    if (e < E) {
        float a = g_al[src[e]] + g_ar[dst[e]];
        g_coef[e] = tanhf(a) * g_norm[e];
    }
}

// ---------------- init scatter target with EPS*raw (folds skip connection + zeroing) ----------------
__global__ void k_init(float4* __restrict__ o4, const float4* __restrict__ raw4, int n4) {
    int i = blockIdx.x * blockDim.x + threadIdx.x;
    if (i < n4) {
        float4 r = raw4[i];
        float4 v; v.x = EPS * r.x; v.y = EPS * r.y; v.z = EPS * r.z; v.w = EPS * r.w;
        o4[i] = v;
    }
}

// ---------------- edge aggregation: warp per edge, red.v4 scatter ----------------
__global__ __launch_bounds__(256) void k_agg(const int* __restrict__ src,
                                             const int* __restrict__ dst,
                                             const float4* __restrict__ h4,
                                             float4* __restrict__ o4, int E) {
    int w = (blockIdx.x * blockDim.x + threadIdx.x) >> 5;
    int lane = threadIdx.x & 31;
    if (w >= E) return;
    int s = __ldg(&src[w]);
    int d = __ldg(&dst[w]);
    float c = g_coef[w];
    float4 v = h4[(size_t)s * 32 + lane];
    float4* p = &o4[(size_t)d * 32 + lane];
    asm volatile("red.global.add.v4.f32 [%0], {%1, %2, %3, %4};"
                 :: "l"(p), "f"(v.x * c), "f"(v.y * c), "f"(v.z * c), "f"(v.w * c)
                 : "memory");
}

// ---------------- GEMM2: emb = h @ t2_w^T + b  [M,128]x[64,128]^T -> [M,64] ----------------
__global__ __launch_bounds__(256) void k_gemm2(const float* __restrict__ H,
                                               const float* __restrict__ W,
                                               const float* __restrict__ B,
                                               float* __restrict__ Emb, int M) {
    __shared__ float As[16][64];
    __shared__ float Bs[16][64];
    const int tid = threadIdx.x;
    const int m0 = blockIdx.x * 64;
    const int lr = tid >> 2;          // 0..63
    const int lk = (tid & 3) * 4;     // 0,4,8,12
    const int tm = (tid >> 4) * 4;    // 0..60
    const int tn = (tid & 15) * 4;    // 0..60

    int gm = m0 + lr;
    if (gm >= M) gm = M - 1;
    const float* hp = H + (size_t)gm * HIDDEN + lk;
    const float* wp = W + (size_t)lr * HIDDEN + lk;

    float acc[4][4];
#pragma unroll
    for (int i = 0; i < 4; i++)
#pragma unroll
        for (int j = 0; j < 4; j++) acc[i][j] = 0.f;

    for (int k0 = 0; k0 < HIDDEN; k0 += 16) {
        float4 xa = *(const float4*)(hp + k0);
        float4 wa = *(const float4*)(wp + k0);
        As[lk + 0][lr] = xa.x; As[lk + 1][lr] = xa.y;
        As[lk + 2][lr] = xa.z; As[lk + 3][lr] = xa.w;
        Bs[lk + 0][lr] = wa.x; Bs[lk + 1][lr] = wa.y;
        Bs[lk + 2][lr] = wa.z; Bs[lk + 3][lr] = wa.w;
        __syncthreads();
#pragma unroll
        for (int kk = 0; kk < 16; kk++) {
            float4 a4 = *(const float4*)&As[kk][tm];
            float4 b4 = *(const float4*)&Bs[kk][tn];
            float a[4] = {a4.x, a4.y, a4.z, a4.w};
            float b[4] = {b4.x, b4.y, b4.z, b4.w};
#pragma unroll
            for (int i = 0; i < 4; i++)
#pragma unroll
                for (int j = 0; j < 4; j++) acc[i][j] = fmaf(a[i], b[j], acc[i][j]);
        }
        __syncthreads();
    }

    float bias[4];
#pragma unroll
    for (int j = 0; j < 4; j++) bias[j] = B[tn + j];
#pragma unroll
    for (int i = 0; i < 4; i++) {
        int m = m0 + tm + i;
        if (m < M) {
            float4 v;
            v.x = acc[i][0] + bias[0];
            v.y = acc[i][1] + bias[1];
            v.z = acc[i][2] + bias[2];
            v.w = acc[i][3] + bias[3];
            *(float4*)(Emb + (size_t)m * OUT_DIM + tn) = v;
        }
    }
}

// ---------------- log_softmax over rows of 64: warp per node ----------------
__global__ __launch_bounds__(256) void k_lsm(const float* __restrict__ emb,
                                             float* __restrict__ out, int M) {
    int w = (blockIdx.x * blockDim.x + threadIdx.x) >> 5;
    int lane = threadIdx.x & 31;
    if (w >= M) return;
    float e0 = emb[(size_t)w * 64 + lane];
    float e1 = emb[(size_t)w * 64 + 32 + lane];
    float m = fmaxf(e0, e1);
#pragma unroll
    for (int off = 16; off > 0; off >>= 1) m = fmaxf(m, __shfl_xor_sync(0xffffffffu, m, off));
    float s = expf(e0 - m) + expf(e1 - m);
#pragma unroll
    for (int off = 16; off > 0; off >>= 1) s += __shfl_xor_sync(0xffffffffu, s, off);
    float lse = m + logf(s);
    out[(size_t)w * 64 + lane] = e0 - lse;
    out[(size_t)w * 64 + 32 + lane] = e1 - lse;
}

// ---------------- launch ----------------
extern "C" void kernel_launch(void* const* d_in, const int* in_sizes, int n_in,
                              void* d_out, int out_size) {
    const float* x    = (const float*)d_in[0];
    const int*   ei   = (const int*)  d_in[1];
    const float* t1w  = (const float*)d_in[2];
    const float* t1b  = (const float*)d_in[3];
    const float* t2w  = (const float*)d_in[4];
    const float* t2b  = (const float*)d_in[5];
    const float* attl = (const float*)d_in[6];
    const float* attr = (const float*)d_in[7];

    const int M = in_sizes[0] / IN_DIM;   // 50000
    const int E = in_sizes[1] / 2;        // 600000
    const int* src = ei;
    const int* dst = ei + E;

    float *raw, *hA, *hB;
    cudaGetSymbolAddress((void**)&raw, g_raw);
    cudaGetSymbolAddress((void**)&hA, g_hA);
    cudaGetSymbolAddress((void**)&hB, g_hB);

    float* out_ls  = (float*)d_out;                       // log_softmax, [M,64]
    float* out_emb = out_ls + (size_t)M * OUT_DIM;        // emb, [M,64]

    // degree / norm
    k_zero_deg<<<(NN + 255) / 256, 256>>>();
    k_deg<<<(E + 255) / 256, 256>>>(dst, E);
    k_dinv<<<(NN + 255) / 256, 256>>>();
    k_norm<<<(E + 255) / 256, 256>>>(src, dst, E);

    // h = relu(x @ t1_w^T + b) -> raw
    k_gemm1<<<(M + 127) / 128, 256>>>(x, t1w, t1b, raw, M);

    const float* cur = raw;
    float* nxt = hA;
    const int n4 = M * HIDDEN / 4;
    for (int l = 0; l < N_LAYERS; l++) {
        k_att<<<((size_t)M * 32 + 255) / 256, 256>>>((const float4*)cur,
                                                     (const float4*)(attl + l * HIDDEN),
                                                     (const float4*)(attr + l * HIDDEN), M);
        k_coef<<<(E + 255) / 256, 256>>>(src, dst, E);
        k_init<<<(n4 + 255) / 256, 256>>>((float4*)nxt, (const float4*)raw, n4);
        k_agg<<<((size_t)E * 32 + 255) / 256, 256>>>(src, dst, (const float4*)cur,
                                                     (float4*)nxt, E);
        cur = nxt;
        nxt = (cur == hA) ? hB : hA;
    }

    // emb + log_softmax
    k_gemm2<<<(M + 63) / 64, 256>>>(cur, t2w, t2b, out_emb, M);
    k_lsm<<<((size_t)M * 32 + 255) / 256, 256>>>(out_emb, out_ls, M);
}

// round 2
// speedup vs baseline: 1.1880x; 1.1880x over previous
#include <cuda_runtime.h>
#include <math.h>

#define NN 50000
#define NE 600000
#define IN_DIM 512
#define HIDDEN 128
#define OUT_DIM 64
#define N_LAYERS 3
#define EPS 0.1f

// ---------------- scratch (static device globals; no allocation) ----------------
__device__ int   g_cnt[NN];
__device__ int   g_off[NN + 1];
__device__ float g_dinv[NN];
__device__ int   g_csr_src[NE];
__device__ int   g_csr_dst[NE];
__device__ float g_norm[NE];      // permuted into CSR order
__device__ float g_coef[NE];      // permuted into CSR order
__device__ float g_al[NN];
__device__ float g_ar[NN];
__device__ float g_raw[(size_t)NN * HIDDEN];
__device__ float g_hA[(size_t)NN * HIDDEN];
__device__ float g_hB[(size_t)NN * HIDDEN];

// ---------------- CSR build ----------------
__global__ void k_zero_cnt() {
    int i = blockIdx.x * blockDim.x + threadIdx.x;
    if (i < NN) g_cnt[i] = 0;
}

__global__ void k_count(const int* __restrict__ dst, int E) {
    int e = blockIdx.x * blockDim.x + threadIdx.x;
    if (e < E) atomicAdd(&g_cnt[dst[e]], 1);
}

// single-block scan over NN counts; also emits dinv and re-zeros cnt
__global__ __launch_bounds__(1024) void k_scan() {
    __shared__ int sh_warp[32];
    __shared__ int sh_carry;
    const int tid = threadIdx.x, lane = tid & 31, wid = tid >> 5;
    if (tid == 0) sh_carry = 0;
    __syncthreads();
    for (int base = 0; base < NN; base += 1024) {
        int i = base + tid;
        int c = (i < NN) ? g_cnt[i] : 0;
        int v = c;
#pragma unroll
        for (int o = 1; o < 32; o <<= 1) {
            int t = __shfl_up_sync(0xffffffffu, v, o);
            if (lane >= o) v += t;
        }
        if (lane == 31) sh_warp[wid] = v;
        __syncthreads();
        if (wid == 0) {
            int s = sh_warp[lane];
#pragma unroll
            for (int o = 1; o < 32; o <<= 1) {
                int t = __shfl_up_sync(0xffffffffu, s, o);
                if (lane >= o) s += t;
            }
            sh_warp[lane] = s;
        }
        __syncthreads();
        int warpoff = (wid > 0) ? sh_warp[wid - 1] : 0;
        int incl = v + warpoff;
        int excl = incl - c + sh_carry;
        if (i < NN) {
            g_off[i] = excl;
            g_dinv[i] = (c > 0) ? rsqrtf((float)c) : 0.f;
            g_cnt[i] = 0;
        }
        __syncthreads();
        if (tid == 1023) sh_carry += incl;
        __syncthreads();
    }
    if (tid == 0) g_off[NN] = sh_carry;
}

__global__ void k_fill(const int* __restrict__ src, const int* __restrict__ dst, int E) {
    int e = blockIdx.x * blockDim.x + threadIdx.x;
    if (e < E) {
        int s = src[e], d = dst[e];
        int pos = g_off[d] + atomicAdd(&g_cnt[d], 1);
        g_csr_src[pos] = s;
        g_csr_dst[pos] = d;
        g_norm[pos] = g_dinv[s] * g_dinv[d];
    }
}

// ---------------- GEMM1: h = relu(x @ t1_w^T + b)  [M,512]x[128,512]^T -> [M,128] ----------------
__global__ __launch_bounds__(256, 2) void k_gemm1(const float* __restrict__ X,
                                                  const float* __restrict__ W,
                                                  const float* __restrict__ B,
                                                  float* __restrict__ O, int M) {
    __shared__ float As[8][128];
    __shared__ float Bs[8][128];
    const int tid = threadIdx.x;
    const int m0 = blockIdx.x * 128;
    const int lr = tid >> 1;
    const int lk = (tid & 1) * 4;
    const int tm = (tid >> 4) * 8;
    const int tn = (tid & 15) * 8;

    int gm = m0 + lr;
    if (gm >= M) gm = M - 1;
    const float* xp = X + (size_t)gm * IN_DIM + lk;
    const float* wp = W + (size_t)lr * IN_DIM + lk;

    float acc[8][8];
#pragma unroll
    for (int i = 0; i < 8; i++)
#pragma unroll
        for (int j = 0; j < 8; j++) acc[i][j] = 0.f;

    for (int k0 = 0; k0 < IN_DIM; k0 += 8) {
        float4 xa = *(const float4*)(xp + k0);
        float4 wa = *(const float4*)(wp + k0);
        As[lk + 0][lr] = xa.x; As[lk + 1][lr] = xa.y;
        As[lk + 2][lr] = xa.z; As[lk + 3][lr] = xa.w;
        Bs[lk + 0][lr] = wa.x; Bs[lk + 1][lr] = wa.y;
        Bs[lk + 2][lr] = wa.z; Bs[lk + 3][lr] = wa.w;
        __syncthreads();
#pragma unroll
        for (int kk = 0; kk < 8; kk++) {
            float4 a0 = *(const float4*)&As[kk][tm];
            float4 a1 = *(const float4*)&As[kk][tm + 4];
            float4 b0 = *(const float4*)&Bs[kk][tn];
            float4 b1 = *(const float4*)&Bs[kk][tn + 4];
            float a[8] = {a0.x, a0.y, a0.z, a0.w, a1.x, a1.y, a1.z, a1.w};
            float b[8] = {b0.x, b0.y, b0.z, b0.w, b1.x, b1.y, b1.z, b1.w};
#pragma unroll
            for (int i = 0; i < 8; i++)
#pragma unroll
                for (int j = 0; j < 8; j++) acc[i][j] = fmaf(a[i], b[j], acc[i][j]);
        }
        __syncthreads();
    }

    float bias[8];
#pragma unroll
    for (int j = 0; j < 8; j++) bias[j] = B[tn + j];
#pragma unroll
    for (int i = 0; i < 8; i++) {
        int m = m0 + tm + i;
        if (m < M) {
            float4 v0, v1;
            v0.x = fmaxf(acc[i][0] + bias[0], 0.f);
            v0.y = fmaxf(acc[i][1] + bias[1], 0.f);
            v0.z = fmaxf(acc[i][2] + bias[2], 0.f);
            v0.w = fmaxf(acc[i][3] + bias[3], 0.f);
            v1.x = fmaxf(acc[i][4] + bias[4], 0.f);
            v1.y = fmaxf(acc[i][5] + bias[5], 0.f);
            v1.z = fmaxf(acc[i][6] + bias[6], 0.f);
            v1.w = fmaxf(acc[i][7] + bias[7], 0.f);
            *(float4*)(O + (size_t)m * HIDDEN + tn) = v0;
            *(float4*)(O + (size_t)m * HIDDEN + tn + 4) = v1;
        }
    }
}

// ---------------- per-node attention dots ----------------
__global__ __launch_bounds__(256) void k_att(const float4* __restrict__ h4,
                                             const float4* __restrict__ attl4,
                                             const float4* __restrict__ attr4, int M) {
    int w = (blockIdx.x * blockDim.x + threadIdx.x) >> 5;
    int lane = threadIdx.x & 31;
    if (w >= M) return;
    float4 hv = h4[(size_t)w * 32 + lane];
    float4 wl = attl4[lane];
    float4 wr = attr4[lane];
    float a = hv.x * wl.x + hv.y * wl.y + hv.z * wl.z + hv.w * wl.w;
    float b = hv.x * wr.x + hv.y * wr.y + hv.z * wr.z + hv.w * wr.w;
#pragma unroll
    for (int off = 16; off > 0; off >>= 1) {
        a += __shfl_xor_sync(0xffffffffu, a, off);
        b += __shfl_xor_sync(0xffffffffu, b, off);
    }
    if (lane == 0) { g_al[w] = a; g_ar[w] = b; }
}

// ---------------- per-edge coefficient (CSR order, coalesced) ----------------
__global__ void k_coef(int E) {
    int e = blockIdx.x * blockDim.x + threadIdx.x;
    if (e < E) {
        int s = g_csr_src[e];
        int d = g_csr_dst[e];
        g_coef[e] = tanhf(g_al[s] + g_ar[d]) * g_norm[e];
    }
}

// ---------------- aggregation: warp-per-node CSR gather (no atomics) ----------------
__global__ __launch_bounds__(256) void k_gather(const float4* __restrict__ h4,
                                                const float4* __restrict__ raw4,
                                                float4* __restrict__ o4, int M) {
    int w = (blockIdx.x * blockDim.x + threadIdx.x) >> 5;
    int lane = threadIdx.x & 31;
    if (w >= M) return;
    int b = g_off[w];
    int e = g_off[w + 1];
    float4 r = raw4[(size_t)w * 32 + lane];
    float4 acc;
    acc.x = EPS * r.x; acc.y = EPS * r.y; acc.z = EPS * r.z; acc.w = EPS * r.w;
    for (int j = b; j < e; j++) {
        int s = __ldg(&g_csr_src[j]);
        float c = __ldg(&g_coef[j]);
        float4 v = h4[(size_t)s * 32 + lane];
        acc.x = fmaf(c, v.x, acc.x);
        acc.y = fmaf(c, v.y, acc.y);
        acc.z = fmaf(c, v.z, acc.z);
        acc.w = fmaf(c, v.w, acc.w);
    }
    o4[(size_t)w * 32 + lane] = acc;
}

// ---------------- GEMM2: emb = h @ t2_w^T + b  [M,128]x[64,128]^T -> [M,64] ----------------
__global__ __launch_bounds__(256) void k_gemm2(const float* __restrict__ H,
                                               const float* __restrict__ W,
                                               const float* __restrict__ B,
                                               float* __restrict__ Emb, int M) {
    __shared__ float As[16][64];
    __shared__ float Bs[16][64];
    const int tid = threadIdx.x;
    const int m0 = blockIdx.x * 64;
    const int lr = tid >> 2;
    const int lk = (tid & 3) * 4;
    const int tm = (tid >> 4) * 4;
    const int tn = (tid & 15) * 4;

    int gm = m0 + lr;
    if (gm >= M) gm = M - 1;
    const float* hp = H + (size_t)gm * HIDDEN + lk;
    const float* wp = W + (size_t)lr * HIDDEN + lk;

    float acc[4][4];
#pragma unroll
    for (int i = 0; i < 4; i++)
#pragma unroll
        for (int j = 0; j < 4; j++) acc[i][j] = 0.f;

    for (int k0 = 0; k0 < HIDDEN; k0 += 16) {
        float4 xa = *(const float4*)(hp + k0);
        float4 wa = *(const float4*)(wp + k0);
        As[lk + 0][lr] = xa.x; As[lk + 1][lr] = xa.y;
        As[lk + 2][lr] = xa.z; As[lk + 3][lr] = xa.w;
        Bs[lk + 0][lr] = wa.x; Bs[lk + 1][lr] = wa.y;
        Bs[lk + 2][lr] = wa.z; Bs[lk + 3][lr] = wa.w;
        __syncthreads();
#pragma unroll
        for (int kk = 0; kk < 16; kk++) {
            float4 a4 = *(const float4*)&As[kk][tm];
            float4 b4 = *(const float4*)&Bs[kk][tn];
            float a[4] = {a4.x, a4.y, a4.z, a4.w};
            float b[4] = {b4.x, b4.y, b4.z, b4.w};
#pragma unroll
            for (int i = 0; i < 4; i++)
#pragma unroll
                for (int j = 0; j < 4; j++) acc[i][j] = fmaf(a[i], b[j], acc[i][j]);
        }
        __syncthreads();
    }

    float bias[4];
#pragma unroll
    for (int j = 0; j < 4; j++) bias[j] = B[tn + j];
#pragma unroll
    for (int i = 0; i < 4; i++) {
        int m = m0 + tm + i;
        if (m < M) {
            float4 v;
            v.x = acc[i][0] + bias[0];
            v.y = acc[i][1] + bias[1];
            v.z = acc[i][2] + bias[2];
            v.w = acc[i][3] + bias[3];
            *(float4*)(Emb + (size_t)m * OUT_DIM + tn) = v;
        }
    }
}

// ---------------- log_softmax over rows of 64: warp per node ----------------
__global__ __launch_bounds__(256) void k_lsm(const float* __restrict__ emb,
                                             float* __restrict__ out, int M) {
    int w = (blockIdx.x * blockDim.x + threadIdx.x) >> 5;
    int lane = threadIdx.x & 31;
    if (w >= M) return;
    float e0 = emb[(size_t)w * 64 + lane];
    float e1 = emb[(size_t)w * 64 + 32 + lane];
    float m = fmaxf(e0, e1);
#pragma unroll
    for (int off = 16; off > 0; off >>= 1) m = fmaxf(m, __shfl_xor_sync(0xffffffffu, m, off));
    float s = expf(e0 - m) + expf(e1 - m);
#pragma unroll
    for (int off = 16; off > 0; off >>= 1) s += __shfl_xor_sync(0xffffffffu, s, off);
    float lse = m + logf(s);
    out[(size_t)w * 64 + lane] = e0 - lse;
    out[(size_t)w * 64 + 32 + lane] = e1 - lse;
}

// ---------------- launch ----------------
extern "C" void kernel_launch(void* const* d_in, const int* in_sizes, int n_in,
                              void* d_out, int out_size) {
    const float* x    = (const float*)d_in[0];
    const int*   ei   = (const int*)  d_in[1];
    const float* t1w  = (const float*)d_in[2];
    const float* t1b  = (const float*)d_in[3];
    const float* t2w  = (const float*)d_in[4];
    const float* t2b  = (const float*)d_in[5];
    const float* attl = (const float*)d_in[6];
    const float* attr = (const float*)d_in[7];

    const int M = in_sizes[0] / IN_DIM;   // 50000
    const int E = in_sizes[1] / 2;        // 600000
    const int* src = ei;
    const int* dst = ei + E;

    float *raw, *hA, *hB;
    cudaGetSymbolAddress((void**)&raw, g_raw);
    cudaGetSymbolAddress((void**)&hA, g_hA);
    cudaGetSymbolAddress((void**)&hB, g_hB);

    float* out_ls  = (float*)d_out;                  // log_softmax [M,64]
    float* out_emb = out_ls + (size_t)M * OUT_DIM;   // emb [M,64]

    // CSR build (per call; edge_index is an input)
    k_zero_cnt<<<(NN + 255) / 256, 256>>>();
    k_count<<<(E + 255) / 256, 256>>>(dst, E);
    k_scan<<<1, 1024>>>();
    k_fill<<<(E + 255) / 256, 256>>>(src, dst, E);

    // h = relu(x @ t1_w^T + b) -> raw (overlaps with CSR build on the GPU)
    k_gemm1<<<(M + 127) / 128, 256>>>(x, t1w, t1b, raw, M);

    const float* cur = raw;
    float* nxt = hA;
    for (int l = 0; l < N_LAYERS; l++) {
        k_att<<<((size_t)M * 32 + 255) / 256, 256>>>((const float4*)cur,
                                                     (const float4*)(attl + l * HIDDEN),
                                                     (const float4*)(attr + l * HIDDEN), M);
        k_coef<<<(E + 255) / 256, 256>>>(E);
        k_gather<<<((size_t)M * 32 + 255) / 256, 256>>>((const float4*)cur,
                                                        (const float4*)raw,
                                                        (float4*)nxt, M);
        cur = nxt;
        nxt = (cur == hA) ? hB : hA;
    }

    // emb + log_softmax
    k_gemm2<<<(M + 63) / 64, 256>>>(cur, t2w, t2b, out_emb, M);
    k_lsm<<<((size_t)M * 32 + 255) / 256, 256>>>(out_emb, out_ls, M);
}

// round 4
// speedup vs baseline: 1.4872x; 1.2519x over previous
#include <cuda_runtime.h>
#include <math.h>

#define NN 50000
#define NE 600000
#define IN_DIM 512
#define HIDDEN 128
#define OUT_DIM 64
#define N_LAYERS 3
#define EPS 0.1f

// ---------------- scratch (static device globals; no allocation) ----------------
__device__ int   g_cnt[NN];
__device__ int   g_off[NN + 4];
__device__ float g_dinv[NN];
__device__ int   g_csr_src[NE];
__device__ float g_norm[NE];      // permuted into CSR order
__device__ float g_alA[NN];
__device__ float g_arA[NN];
__device__ float g_alB[NN];
__device__ float g_arB[NN];
__device__ float g_raw[(size_t)NN * HIDDEN];
__device__ float g_hA[(size_t)NN * HIDDEN];
__device__ float g_hB[(size_t)NN * HIDDEN];

// ---------------- CSR build ----------------
__global__ void k_zero_cnt() {
    int i = blockIdx.x * blockDim.x + threadIdx.x;
    if (i < NN) g_cnt[i] = 0;
}

__global__ void k_count(const int* __restrict__ dst, int E) {
    int e = blockIdx.x * blockDim.x + threadIdx.x;
    if (e < E) atomicAdd(&g_cnt[dst[e]], 1);
}

// single-block scan over NN counts (int4 per thread); emits off, dinv, re-zeros cnt
__global__ __launch_bounds__(1024) void k_scan() {
    __shared__ int sh_warp[32];
    __shared__ int sh_carry;
    const int tid = threadIdx.x, lane = tid & 31, wid = tid >> 5;
    if (tid == 0) sh_carry = 0;
    __syncthreads();
    for (int base = 0; base < NN; base += 4096) {
        int idx = base + tid * 4;
        int4 c = make_int4(0, 0, 0, 0);
        if (idx < NN) c = *(const int4*)&g_cnt[idx];
        int t = c.x + c.y + c.z + c.w;
        int v = t;
#pragma unroll
        for (int o = 1; o < 32; o <<= 1) {
            int tt = __shfl_up_sync(0xffffffffu, v, o);
            if (lane >= o) v += tt;
        }
        if (lane == 31) sh_warp[wid] = v;
        __syncthreads();
        if (wid == 0) {
            int s = sh_warp[lane];
#pragma unroll
            for (int o = 1; o < 32; o <<= 1) {
                int tt = __shfl_up_sync(0xffffffffu, s, o);
                if (lane >= o) s += tt;
            }
            sh_warp[lane] = s;
        }
        __syncthreads();
        int warpoff = (wid > 0) ? sh_warp[wid - 1] : 0;
        int incl = v + warpoff;
        int excl = incl - t + sh_carry;
        if (idx < NN) {
            int4 off;
            off.x = excl;
            off.y = off.x + c.x;
            off.z = off.y + c.y;
            off.w = off.z + c.z;
            *(int4*)&g_off[idx] = off;
            float4 dv;
            dv.x = c.x ? rsqrtf((float)c.x) : 0.f;
            dv.y = c.y ? rsqrtf((float)c.y) : 0.f;
            dv.z = c.z ? rsqrtf((float)c.z) : 0.f;
            dv.w = c.w ? rsqrtf((float)c.w) : 0.f;
            *(float4*)&g_dinv[idx] = dv;
            *(int4*)&g_cnt[idx] = make_int4(0, 0, 0, 0);
        }
        __syncthreads();
        if (tid == 1023) sh_carry += incl;
        __syncthreads();
    }
    if (tid == 0) g_off[NN] = sh_carry;
}

__global__ void k_fill(const int* __restrict__ src, const int* __restrict__ dst, int E) {
    int e = blockIdx.x * blockDim.x + threadIdx.x;
    if (e < E) {
        int s = src[e], d = dst[e];
        int pos = g_off[d] + atomicAdd(&g_cnt[d], 1);
        g_csr_src[pos] = s;
        g_norm[pos] = g_dinv[s] * g_dinv[d];
    }
}

// ---------------- GEMM1 (double-buffered) + fused att dots for layer 0 ----------------
__global__ __launch_bounds__(256, 2) void k_gemm1(const float* __restrict__ X,
                                                  const float* __restrict__ W,
                                                  const float* __restrict__ B,
                                                  const float* __restrict__ attL,
                                                  const float* __restrict__ attR,
                                                  float* __restrict__ al_out,
                                                  float* __restrict__ ar_out,
                                                  float* __restrict__ O, int M) {
    __shared__ float As[2][8][128];
    __shared__ float Bs[2][8][128];
    const int tid = threadIdx.x;
    const int m0 = blockIdx.x * 128;
    const int lr = tid >> 1;          // 0..127
    const int lk = (tid & 1) * 4;     // 0 or 4
    const int tm = (tid >> 4) * 8;    // row group
    const int tn = (tid & 15) * 8;    // col group

    int gm = m0 + lr;
    if (gm >= M) gm = M - 1;
    const float* xp = X + (size_t)gm * IN_DIM + lk;
    const float* wp = W + (size_t)lr * IN_DIM + lk;

    float acc[8][8];
#pragma unroll
    for (int i = 0; i < 8; i++)
#pragma unroll
        for (int j = 0; j < 8; j++) acc[i][j] = 0.f;

    {
        float4 xa = *(const float4*)(xp);
        float4 wa = *(const float4*)(wp);
        As[0][lk + 0][lr] = xa.x; As[0][lk + 1][lr] = xa.y;
        As[0][lk + 2][lr] = xa.z; As[0][lk + 3][lr] = xa.w;
        Bs[0][lk + 0][lr] = wa.x; Bs[0][lk + 1][lr] = wa.y;
        Bs[0][lk + 2][lr] = wa.z; Bs[0][lk + 3][lr] = wa.w;
    }
    __syncthreads();

    int buf = 0;
    for (int k0 = 0; k0 < IN_DIM - 8; k0 += 8) {
        float4 xa = *(const float4*)(xp + k0 + 8);
        float4 wa = *(const float4*)(wp + k0 + 8);
#pragma unroll
        for (int kk = 0; kk < 8; kk++) {
            float4 a0 = *(const float4*)&As[buf][kk][tm];
            float4 a1 = *(const float4*)&As[buf][kk][tm + 4];
            float4 b0 = *(const float4*)&Bs[buf][kk][tn];
            float4 b1 = *(const float4*)&Bs[buf][kk][tn + 4];
            float a[8] = {a0.x, a0.y, a0.z, a0.w, a1.x, a1.y, a1.z, a1.w};
            float b[8] = {b0.x, b0.y, b0.z, b0.w, b1.x, b1.y, b1.z, b1.w};
#pragma unroll
            for (int i = 0; i < 8; i++)
#pragma unroll
                for (int j = 0; j < 8; j++) acc[i][j] = fmaf(a[i], b[j], acc[i][j]);
        }
        int nb = buf ^ 1;
        As[nb][lk + 0][lr] = xa.x; As[nb][lk + 1][lr] = xa.y;
        As[nb][lk + 2][lr] = xa.z; As[nb][lk + 3][lr] = xa.w;
        Bs[nb][lk + 0][lr] = wa.x; Bs[nb][lk + 1][lr] = wa.y;
        Bs[nb][lk + 2][lr] = wa.z; Bs[nb][lk + 3][lr] = wa.w;
        __syncthreads();
        buf = nb;
    }
#pragma unroll
    for (int kk = 0; kk < 8; kk++) {
        float4 a0 = *(const float4*)&As[buf][kk][tm];
        float4 a1 = *(const float4*)&As[buf][kk][tm + 4];
        float4 b0 = *(const float4*)&Bs[buf][kk][tn];
        float4 b1 = *(const float4*)&Bs[buf][kk][tn + 4];
        float a[8] = {a0.x, a0.y, a0.z, a0.w, a1.x, a1.y, a1.z, a1.w};
        float b[8] = {b0.x, b0.y, b0.z, b0.w, b1.x, b1.y, b1.z, b1.w};
#pragma unroll
        for (int i = 0; i < 8; i++)
#pragma unroll
            for (int j = 0; j < 8; j++) acc[i][j] = fmaf(a[i], b[j], acc[i][j]);
    }

    float bias[8], wl[8], wr[8];
#pragma unroll
    for (int j = 0; j < 8; j++) {
        bias[j] = B[tn + j];
        wl[j] = attL[tn + j];
        wr[j] = attR[tn + j];
    }
#pragma unroll
    for (int i = 0; i < 8; i++) {
        int m = m0 + tm + i;
        float v[8];
#pragma unroll
        for (int j = 0; j < 8; j++) v[j] = fmaxf(acc[i][j] + bias[j], 0.f);
        float sl = 0.f, sr = 0.f;
#pragma unroll
        for (int j = 0; j < 8; j++) {
            sl = fmaf(v[j], wl[j], sl);
            sr = fmaf(v[j], wr[j], sr);
        }
#pragma unroll
        for (int o = 8; o > 0; o >>= 1) {
            sl += __shfl_xor_sync(0xffffffffu, sl, o);
            sr += __shfl_xor_sync(0xffffffffu, sr, o);
        }
        if (m < M) {
            float4 v0 = make_float4(v[0], v[1], v[2], v[3]);
            float4 v1 = make_float4(v[4], v[5], v[6], v[7]);
            *(float4*)(O + (size_t)m * HIDDEN + tn) = v0;
            *(float4*)(O + (size_t)m * HIDDEN + tn + 4) = v1;
            if ((tid & 15) == 0) { al_out[m] = sl; ar_out[m] = sr; }
        }
    }
}

// ---------------- aggregation: warp-per-node CSR gather, fused coef + next-layer att ----------------
// al_in/ar_in and al_out/ar_out MUST be distinct buffers (race otherwise).
__global__ __launch_bounds__(256) void k_gather(const float4* __restrict__ h4,
                                                const float4* __restrict__ raw4,
                                                float4* __restrict__ o4,
                                                const float* __restrict__ al_in,
                                                const float* __restrict__ ar_in,
                                                const float4* __restrict__ attl_next,
                                                const float4* __restrict__ attr_next,
                                                float* __restrict__ al_out,
                                                float* __restrict__ ar_out,
                                                int M) {
    int w = (blockIdx.x * blockDim.x + threadIdx.x) >> 5;
    int lane = threadIdx.x & 31;
    if (w >= M) return;
    int b = g_off[w];
    int e = g_off[w + 1];
    float ar_w = ar_in[w];
    float4 r = raw4[(size_t)w * 32 + lane];
    float4 acc;
    acc.x = EPS * r.x; acc.y = EPS * r.y; acc.z = EPS * r.z; acc.w = EPS * r.w;

    for (int j0 = b; j0 < e; j0 += 32) {
        int jj = j0 + lane;
        float cl = 0.f;
        int sl = 0;
        if (jj < e) {
            sl = __ldg(&g_csr_src[jj]);
            float nrm = __ldg(&g_norm[jj]);
            cl = tanhf(al_in[sl] + ar_w) * nrm;
        }
        int cnt = min(32, e - j0);
        for (int k = 0; k < cnt; k++) {
            float c = __shfl_sync(0xffffffffu, cl, k);
            int s = __shfl_sync(0xffffffffu, sl, k);
            float4 v = h4[(size_t)s * 32 + lane];
            acc.x = fmaf(c, v.x, acc.x);
            acc.y = fmaf(c, v.y, acc.y);
            acc.z = fmaf(c, v.z, acc.z);
            acc.w = fmaf(c, v.w, acc.w);
        }
    }
    o4[(size_t)w * 32 + lane] = acc;

    if (attl_next) {
        float4 wl = attl_next[lane];
        float4 wr = attr_next[lane];
        float a = acc.x * wl.x + acc.y * wl.y + acc.z * wl.z + acc.w * wl.w;
        float bb = acc.x * wr.x + acc.y * wr.y + acc.z * wr.z + acc.w * wr.w;
#pragma unroll
        for (int o = 16; o > 0; o >>= 1) {
            a += __shfl_xor_sync(0xffffffffu, a, o);
            bb += __shfl_xor_sync(0xffffffffu, bb, o);
        }
        if (lane == 0) { al_out[w] = a; ar_out[w] = bb; }
    }
}

// ---------------- GEMM2 + fused log_softmax ----------------
__global__ __launch_bounds__(256) void k_gemm2(const float* __restrict__ H,
                                               const float* __restrict__ W,
                                               const float* __restrict__ B,
                                               float* __restrict__ Emb,
                                               float* __restrict__ Ls, int M) {
    __shared__ float As[16][64];
    __shared__ float Bs[16][64];
    const int tid = threadIdx.x;
    const int m0 = blockIdx.x * 64;
    const int lr = tid >> 2;
    const int lk = (tid & 3) * 4;
    const int tm = (tid >> 4) * 4;
    const int tn = (tid & 15) * 4;

    int gm = m0 + lr;
    if (gm >= M) gm = M - 1;
    const float* hp = H + (size_t)gm * HIDDEN + lk;
    const float* wp = W + (size_t)lr * HIDDEN + lk;

    float acc[4][4];
#pragma unroll
    for (int i = 0; i < 4; i++)
#pragma unroll
        for (int j = 0; j < 4; j++) acc[i][j] = 0.f;

    for (int k0 = 0; k0 < HIDDEN; k0 += 16) {
        float4 xa = *(const float4*)(hp + k0);
        float4 wa = *(const float4*)(wp + k0);
        As[lk + 0][lr] = xa.x; As[lk + 1][lr] = xa.y;
        As[lk + 2][lr] = xa.z; As[lk + 3][lr] = xa.w;
        Bs[lk + 0][lr] = wa.x; Bs[lk + 1][lr] = wa.y;
        Bs[lk + 2][lr] = wa.z; Bs[lk + 3][lr] = wa.w;
        __syncthreads();
#pragma unroll
        for (int kk = 0; kk < 16; kk++) {
            float4 a4 = *(const float4*)&As[kk][tm];
            float4 b4 = *(const float4*)&Bs[kk][tn];
            float a[4] = {a4.x, a4.y, a4.z, a4.w};
            float b[4] = {b4.x, b4.y, b4.z, b4.w};
#pragma unroll
            for (int i = 0; i < 4; i++)
#pragma unroll
                for (int j = 0; j < 4; j++) acc[i][j] = fmaf(a[i], b[j], acc[i][j]);
        }
        __syncthreads();
    }

    float bias[4];
#pragma unroll
    for (int j = 0; j < 4; j++) bias[j] = B[tn + j];

#pragma unroll
    for (int i = 0; i < 4; i++) {
        int m = m0 + tm + i;
        float v[4];
#pragma unroll
        for (int j = 0; j < 4; j++) v[j] = acc[i][j] + bias[j];
        float mx = fmaxf(fmaxf(v[0], v[1]), fmaxf(v[2], v[3]));
#pragma unroll
        for (int o = 8; o > 0; o >>= 1) mx = fmaxf(mx, __shfl_xor_sync(0xffffffffu, mx, o));
        float s = expf(v[0] - mx) + expf(v[1] - mx) + expf(v[2] - mx) + expf(v[3] - mx);
#pragma unroll
        for (int o = 8; o > 0; o >>= 1) s += __shfl_xor_sync(0xffffffffu, s, o);
        float lse = mx + logf(s);
        if (m < M) {
            float4 ev = make_float4(v[0], v[1], v[2], v[3]);
            float4 lv = make_float4(v[0] - lse, v[1] - lse, v[2] - lse, v[3] - lse);
            *(float4*)(Emb + (size_t)m * OUT_DIM + tn) = ev;
            *(float4*)(Ls + (size_t)m * OUT_DIM + tn) = lv;
        }
    }
}

// ---------------- launch ----------------
extern "C" void kernel_launch(void* const* d_in, const int* in_sizes, int n_in,
                              void* d_out, int out_size) {
    const float* x    = (const float*)d_in[0];
    const int*   ei   = (const int*)  d_in[1];
    const float* t1w  = (const float*)d_in[2];
    const float* t1b  = (const float*)d_in[3];
    const float* t2w  = (const float*)d_in[4];
    const float* t2b  = (const float*)d_in[5];
    const float* attl = (const float*)d_in[6];
    const float* attr = (const float*)d_in[7];

    const int M = in_sizes[0] / IN_DIM;   // 50000
    const int E = in_sizes[1] / 2;        // 600000
    const int* src = ei;
    const int* dst = ei + E;

    float *raw, *hA, *hB, *alA, *arA, *alB, *arB;
    cudaGetSymbolAddress((void**)&raw, g_raw);
    cudaGetSymbolAddress((void**)&hA, g_hA);
    cudaGetSymbolAddress((void**)&hB, g_hB);
    cudaGetSymbolAddress((void**)&alA, g_alA);
    cudaGetSymbolAddress((void**)&arA, g_arA);
    cudaGetSymbolAddress((void**)&alB, g_alB);
    cudaGetSymbolAddress((void**)&arB, g_arB);

    float* out_ls  = (float*)d_out;                  // log_softmax [M,64]
    float* out_emb = out_ls + (size_t)M * OUT_DIM;   // emb [M,64]

    // CSR build
    k_zero_cnt<<<(NN + 255) / 256, 256>>>();
    k_count<<<(E + 255) / 256, 256>>>(dst, E);
    k_scan<<<1, 1024>>>();
    k_fill<<<(E + 255) / 256, 256>>>(src, dst, E);

    // h = relu(x @ t1_w^T + b) -> raw; fused att dots (layer 0) -> buffers A
    k_gemm1<<<(M + 127) / 128, 256>>>(x, t1w, t1b, attl, attr, alA, arA, raw, M);

    const float* cur = raw;
    float* nxt = hA;
    for (int l = 0; l < N_LAYERS; l++) {
        const float* anl = (l + 1 < N_LAYERS) ? (attl + (l + 1) * HIDDEN) : nullptr;
        const float* anr = (l + 1 < N_LAYERS) ? (attr + (l + 1) * HIDDEN) : nullptr;
        const float* al_in = (l & 1) ? alB : alA;
        const float* ar_in = (l & 1) ? arB : arA;
        float* al_out = (l & 1) ? alA : alB;
        float* ar_out = (l & 1) ? arA : arB;
        k_gather<<<((size_t)M * 32 + 255) / 256, 256>>>((const float4*)cur,
                                                        (const float4*)raw,
                                                        (float4*)nxt,
                                                        al_in, ar_in,
                                                        (const float4*)anl,
                                                        (const float4*)anr,
                                                        al_out, ar_out, M);
        cur = nxt;
        nxt = (cur == hA) ? hB : hA;
    }

    // emb + fused log_softmax
    k_gemm2<<<(M + 63) / 64, 256>>>(cur, t2w, t2b, out_emb, out_ls, M);
}